// round 15
// baseline (speedup 1.0000x reference)
#include <cuda_runtime.h>
#include <cuda_bf16.h>
#include <cstdint>

// Problem constants (fixed by dataset)
#define NV    4096          // N = H*W
#define WW    64            // width
#define CAP   128           // row/col bucket capacity (Binomial mean 20, max ~50)
#define ECAP  512           // per-row LOC/IU off-diag bin capacity
#define NNZCM 81920
#define MLOC  2048
#define MIU   2048
#define NWORK (NNZCM + MLOC * 9 + MIU * 5)   // 110592
#define NTHR  512
#define GRID  592           // 148 SMs * 4 blocks; launch_bounds(512,4) guarantees
                            // co-residency for the software grid barrier
#define NPRE  3             // prefetch depth for outer rounds (covers tc <= 47)

// Scratch (static device globals). Buckets store packed (index, value-bits)
// pairs -> single 8B load per entry on the gather path.
__device__ int   g_rcnt[NV];            // row-bucket counts (Lcm rows)
__device__ float g_rowsum[NV];          // Wcm row sums
__device__ int2  g_rpak[NV * CAP];      // row buckets: {col, val bits}
__device__ int   g_ccnt[NV];            // col-bucket counts (Lcm columns)
__device__ int2  g_cpak[NV * CAP];      // col buckets: {row k, val bits}
__device__ int   g_ecnt[NV];            // per-row LOC/IU off-diag bin counts
__device__ int2  g_epak[NV * ECAP];     // LOC/IU bins: {col, val bits}
__device__ float g_ediag[NV];           // LOC/IU diagonal accumulator

// Barrier state (zero-initialized; last finisher resets -> identical every call)
__device__ unsigned          g_barc[2];
__device__ volatile unsigned g_rel[2];
__device__ unsigned          g_fin;

__device__ __forceinline__ void grid_barrier(int which) {
    __syncthreads();
    if (threadIdx.x == 0) {
        __threadfence();                       // release: my writes -> L2
        unsigned t = atomicAdd(&g_barc[which], 1);
        if (t == GRID - 1) g_rel[which] = 1;   // volatile store
        else while (g_rel[which] == 0) __nanosleep(32);
        __threadfence();
    }
    __syncthreads();
}

__device__ __forceinline__ void push_e(int r, int c, float v) {
    int s = atomicAdd(&g_ecnt[r], 1);
    if (s < ECAP) g_epak[r * ECAP + s] = make_int2(c, __float_as_int(v));
}

__device__ __forceinline__ uint32_t smem_u32(const void* p) {
    return (uint32_t)__cvta_generic_to_shared(p);
}

// ---------------------------------------------------------------------------
// Single persistent kernel: reset -> barrier -> build -> barrier -> rows.
// Rows phase: A[r][:] = sum over T(r) of w * (dense row k of Lcm); see R14.
// Double-buffered SMEM row accumulators + TMA bulk stores keep the write
// path fully off the warp-issue critical path.
__global__ void __launch_bounds__(NTHR, 4)
k_all(float* __restrict__ A,
      float* __restrict__ b,
      const int* __restrict__ Wcm_row,
      const int* __restrict__ Wcm_col,
      const float* __restrict__ Wcm_data,
      const float* __restrict__ cmw,
      const int* __restrict__ LOC_inInd,
      const float* __restrict__ LOC_flows,   // (9,9,MLOC)
      const float* __restrict__ locw,
      const int* __restrict__ IU_inInd,
      const float* __restrict__ IU_flows,    // (MIU,5)
      const int* __restrict__ IU_neigh,      // (MIU,5)
      const float* __restrict__ iuw,
      const float* __restrict__ kuw,
      const float* __restrict__ kToUconf,
      const float* __restrict__ known,
      const float* __restrict__ kToU,
      const float* __restrict__ lmbda) {
    const int tid = threadIdx.x;
    const int blk = blockIdx.x;
    const int gtid = blk * NTHR + tid;

    // ---- Phase 0: zero per-row counters ----
    if (gtid < NV) {
        g_rcnt[gtid] = 0; g_ccnt[gtid] = 0; g_ecnt[gtid] = 0;
        g_rowsum[gtid] = 0.0f; g_ediag[gtid] = 0.0f;
    }
    grid_barrier(0);

    // ---- Phase 1: build buckets/bins (GRID*NTHR = 303104 >= NWORK: one pass)
    {
        int t = gtid;
        if (t < NNZCM) {
            int r = Wcm_row[t];
            int c = Wcm_col[t];
            float v = Wcm_data[t] * __ldg(&cmw[r]);
            int s = atomicAdd(&g_rcnt[r], 1);
            if (s < CAP) g_rpak[r * CAP + s] = make_int2(c, __float_as_int(v));
            int s2 = atomicAdd(&g_ccnt[c], 1);
            if (s2 < CAP) g_cpak[c * CAP + s2] = make_int2(r, __float_as_int(v));
            atomicAdd(&g_rowsum[r], v);
        } else if (t < NNZCM + MLOC * 9) {
            int u = t - NNZCM;
            int m = u & (MLOC - 1);
            int j = u >> 11;                    // MLOC = 2048
            const int offs[9] = { -1 - WW, -1, -1 + WW, -WW, 0, WW, 1 - WW, 1, 1 + WW };
            int base = __ldg(&LOC_inInd[m]);
            int r0 = base + offs[0];
            int c  = base + offs[j];
            float h = 0.5f * __ldg(&LOC_flows[(size_t)j * 9 * MLOC + m]) * __ldg(&locw[base]);
            push_e(r0, c, -h);
            push_e(c, r0, -h);
            atomicAdd(&g_ediag[r0], h);
            atomicAdd(&g_ediag[c],  h);
        } else if (t < NWORK) {
            int u = t - NNZCM - MLOC * 9;
            int m = u / 5;
            int j = u - m * 5;
            int r = __ldg(&IU_inInd[m]);
            int c = __ldg(&IU_neigh[m * 5 + j]);
            float h = 0.5f * __ldg(&IU_flows[m * 5 + j]) * __ldg(&iuw[r]);
            push_e(r, c, -h);
            push_e(c, r, -h);
            atomicAdd(&g_ediag[r], h);
            atomicAdd(&g_ediag[c], h);
        }
    }
    grid_barrier(1);

    // ---- Phase 2: assemble rows r = blk, blk+GRID, ... (~7 rows/block) ----
    __shared__ float buf[2][NV];               // 2 x 16 KB double-buffered row
    __shared__ int   s_k [CAP + 1];            // staged outer entries of T(r)
    __shared__ float s_w [CAP + 1];
    __shared__ int   s_nk[CAP + 1];
    __shared__ float s_rs[CAP + 1];
    const int wid  = tid >> 5;                 // 0..15
    const int lane = tid & 31;
    const float4 z = make_float4(0.f, 0.f, 0.f, 0.f);
    const float lam = __ldg(&lmbda[0]);
    int pb = 0;

    for (int r = blk; r < NV; r += GRID, pb ^= 1) {
        float* bufp = buf[pb];
        float4* buf4 = (float4*)bufp;

        // Ensure the TMA issued 2 rows ago (same parity buffer) finished
        // reading this buffer; the 1-rows-ago group may still be in flight.
        if (tid == 0)
            asm volatile("cp.async.bulk.wait_group.read 1;" ::: "memory");
        __syncthreads();

        // Stage A: batch-load ALL outer entries (k, w) and their (nk, rowsum)
        // into SMEM; latency overlaps the buffer-zero loop below.
        int tc = min(__ldcg(&g_ccnt[r]), CAP);
        if (tid <= tc) {
            int k; float w;
            if (tid < tc) {
                int2 p = __ldcg(&g_cpak[r * CAP + tid]);
                k = p.x; w = -__int_as_float(p.y);
            } else {
                k = r; w = __ldcg(&g_rowsum[r]);       // diagonal of col r
            }
            s_k[tid]  = k;
            s_w[tid]  = w;
            s_nk[tid] = min(__ldcg(&g_rcnt[k]), CAP);
            s_rs[tid] = __ldcg(&g_rowsum[k]);
        }
        for (int i = tid; i < NV / 4; i += NTHR) buf4[i] = z;
        __syncthreads();

        // Stage B: warp per outer entry (16 warps; typically <=2 rounds).
        // Prefetch the first inner batch of up to NPRE rounds back-to-back
        // (MLP), then do the atomics.
        int2 pre[NPRE];
        #pragma unroll
        for (int j = 0; j < NPRE; j++) {
            int o = wid + j * 16;
            if (o <= tc && lane < s_nk[o])
                pre[j] = __ldcg(&g_rpak[s_k[o] * CAP + lane]);
        }
        #pragma unroll
        for (int j = 0; j < NPRE; j++) {
            int o = wid + j * 16;
            if (o > tc) break;
            int   k  = s_k[o];
            float w  = s_w[o];
            int   nk = s_nk[o];
            if (lane <= nk) {
                int c2; float v2;
                if (lane < nk) { c2 = pre[j].x; v2 = -__int_as_float(pre[j].y); }
                else           { c2 = k;        v2 = s_rs[o]; }   // diag of row k
                atomicAdd(&bufp[c2], w * v2);
            }
            for (int i = lane + 32; i <= nk; i += 32) {           // rare tail
                int c2; float v2;
                if (i < nk) {
                    int2 q = __ldcg(&g_rpak[k * CAP + i]);
                    c2 = q.x; v2 = -__int_as_float(q.y);
                } else { c2 = k; v2 = s_rs[o]; }
                atomicAdd(&bufp[c2], w * v2);
            }
        }
        for (int o = wid + NPRE * 16; o <= tc; o += 16) {         // very rare
            int   k  = s_k[o];
            float w  = s_w[o];
            int   nk = s_nk[o];
            for (int i = lane; i <= nk; i += 32) {
                int c2; float v2;
                if (i < nk) {
                    int2 q = __ldcg(&g_rpak[k * CAP + i]);
                    c2 = q.x; v2 = -__int_as_float(q.y);
                } else { c2 = k; v2 = s_rs[o]; }
                atomicAdd(&bufp[c2], w * v2);
            }
        }

        // binned LOC/IU off-diagonal contributions
        int ne = min(__ldcg(&g_ecnt[r]), ECAP);
        for (int i = tid; i < ne; i += NTHR) {
            int2 q = __ldcg(&g_epak[r * ECAP + i]);
            atomicAdd(&bufp[q.x], __int_as_float(q.y));
        }

        // diagonal (LOC/IU diag + regularization) + RHS
        if (tid == 0) {
            float d = __ldg(&kuw[r]) * __ldg(&kToUconf[r]) + lam * __ldg(&known[r]);
            atomicAdd(&bufp[r], d + __ldcg(&g_ediag[r]));
            b[r] = d * __ldg(&kToU[r]);
        }
        __syncthreads();

        // TMA bulk store: 16 KB SMEM row -> GMEM, fully async (next row works
        // in the other buffer while this drains).
        if (tid == 0) {
            asm volatile("fence.proxy.async.shared::cta;" ::: "memory");
            asm volatile(
                "cp.async.bulk.global.shared::cta.bulk_group [%0], [%1], %2;"
                :: "l"(A + (size_t)r * NV), "r"(smem_u32(bufp)), "n"(NV * 4)
                : "memory");
            asm volatile("cp.async.bulk.commit_group;" ::: "memory");
        }
    }

    // Drain outstanding TMA stores before exit.
    if (tid == 0)
        asm volatile("cp.async.bulk.wait_group 0;" ::: "memory");

    // ---- Reset barrier state for the next call (last finisher) ----
    if (tid == 0) {
        __threadfence();
        unsigned t = atomicAdd(&g_fin, 1);
        if (t == GRID - 1) {
            g_barc[0] = 0; g_barc[1] = 0;
            g_rel[0]  = 0; g_rel[1]  = 0;
            __threadfence();
            g_fin = 0;
        }
    }
}

// ---------------------------------------------------------------------------
extern "C" void kernel_launch(void* const* d_in, const int* in_sizes, int n_in,
                              void* d_out, int out_size) {
    const float* CM_weights  = (const float*)d_in[2];
    const float* LOC_weights = (const float*)d_in[3];
    const float* IU_weights  = (const float*)d_in[4];
    const float* KU_weights  = (const float*)d_in[5];
    const float* lmbda       = (const float*)d_in[6];
    const float* kToUconf    = (const float*)d_in[7];
    const float* known       = (const float*)d_in[8];
    const float* kToU        = (const float*)d_in[9];
    const int*   Wcm_row     = (const int*)d_in[10];
    const int*   Wcm_col     = (const int*)d_in[11];
    const float* Wcm_data    = (const float*)d_in[12];
    const int*   LOC_inInd   = (const int*)d_in[13];
    const float* LOC_flows   = (const float*)d_in[14];
    const int*   IU_inInd    = (const int*)d_in[15];
    const float* IU_flows    = (const float*)d_in[16];
    const int*   IU_neighInd = (const int*)d_in[17];

    float* A = (float*)d_out;
    float* b = (float*)d_out + (size_t)NV * NV;

    k_all<<<GRID, NTHR>>>(A, b,
                          Wcm_row, Wcm_col, Wcm_data, CM_weights,
                          LOC_inInd, LOC_flows, LOC_weights,
                          IU_inInd, IU_flows, IU_neighInd, IU_weights,
                          KU_weights, kToUconf, known, kToU, lmbda);
}

// round 17
// speedup vs baseline: 1.2156x; 1.2156x over previous
#include <cuda_runtime.h>
#include <cuda_bf16.h>
#include <cstdint>

// Problem constants (fixed by dataset)
#define NV    4096          // N = H*W
#define WW    64            // width
#define CAP   128           // row/col bucket capacity (Binomial mean 20, max ~50)
#define ECAP  512           // per-row LOC/IU off-diag bin capacity
#define NNZCM 81920
#define MLOC  2048
#define MIU   2048
#define NWORK (NNZCM + MLOC * 9 + MIU * 5)   // 110592
#define NTHR  256
#define GRID  1024          // exactly 4 rows/block; < 148*8 resident -> barrier safe
#define NPRE  4             // prefetch depth: covers outer entries o <= 31

// Scratch (static device globals). Buckets store packed (index, value-bits)
// pairs -> single 8B load per entry on the gather path.
__device__ int   g_rcnt[NV];            // row-bucket counts (Lcm rows)
__device__ float g_rowsum[NV];          // Wcm row sums
__device__ int2  g_rpak[NV * CAP];      // row buckets: {col, val bits}
__device__ int   g_ccnt[NV];            // col-bucket counts (Lcm columns)
__device__ int2  g_cpak[NV * CAP];      // col buckets: {row k, val bits}
__device__ int   g_ecnt[NV];            // per-row LOC/IU off-diag bin counts
__device__ int2  g_epak[NV * ECAP];     // LOC/IU bins: {col, val bits}
__device__ float g_ediag[NV];           // LOC/IU diagonal accumulator

// Barrier state (zero-initialized; last finisher resets -> identical every call)
__device__ unsigned          g_barc[2];
__device__ volatile unsigned g_rel[2];
__device__ unsigned          g_fin;

__device__ __forceinline__ void grid_barrier(int which) {
    __syncthreads();
    if (threadIdx.x == 0) {
        __threadfence();                       // release: my writes -> L2
        unsigned t = atomicAdd(&g_barc[which], 1);
        if (t == GRID - 1) g_rel[which] = 1;   // volatile store
        else while (g_rel[which] == 0) __nanosleep(32);
        __threadfence();
    }
    __syncthreads();
}

__device__ __forceinline__ void push_e(int r, int c, float v) {
    int s = atomicAdd(&g_ecnt[r], 1);
    if (s < ECAP) g_epak[r * ECAP + s] = make_int2(c, __float_as_int(v));
}

__device__ __forceinline__ uint32_t smem_u32(const void* p) {
    return (uint32_t)__cvta_generic_to_shared(p);
}

// ---------------------------------------------------------------------------
// Single persistent kernel: reset -> barrier -> build -> barrier -> rows.
// Rows phase: A[r][:] = sum over T(r) of w * (dense row k of Lcm), with
//   T(r) = {(k,-v_e): CM entry e with col==r} ∪ {(r, rowsum_r)} and
//   row_k = [(c_e,-v_e)] ∪ [(k, rowsum_k)]. Duplicates need no dedup
//   (bilinearity). SMEM row accumulator + shared atomics; finished row
//   leaves via TMA bulk store (off the warp-issue path). No zero pass over
//   A; no global atomics into A.
__global__ void __launch_bounds__(NTHR, 8)
k_all(float* __restrict__ A,
      float* __restrict__ b,
      const int* __restrict__ Wcm_row,
      const int* __restrict__ Wcm_col,
      const float* __restrict__ Wcm_data,
      const float* __restrict__ cmw,
      const int* __restrict__ LOC_inInd,
      const float* __restrict__ LOC_flows,   // (9,9,MLOC)
      const float* __restrict__ locw,
      const int* __restrict__ IU_inInd,
      const float* __restrict__ IU_flows,    // (MIU,5)
      const int* __restrict__ IU_neigh,      // (MIU,5)
      const float* __restrict__ iuw,
      const float* __restrict__ kuw,
      const float* __restrict__ kToUconf,
      const float* __restrict__ known,
      const float* __restrict__ kToU,
      const float* __restrict__ lmbda) {
    const int tid = threadIdx.x;
    const int blk = blockIdx.x;
    const int gtid = blk * NTHR + tid;

    // ---- Phase 0: zero per-row counters ----
    if (gtid < NV) {
        g_rcnt[gtid] = 0; g_ccnt[gtid] = 0; g_ecnt[gtid] = 0;
        g_rowsum[gtid] = 0.0f; g_ediag[gtid] = 0.0f;
    }
    grid_barrier(0);

    // ---- Phase 1: build buckets/bins (GRID*NTHR = 262144 >= NWORK: one pass)
    {
        int t = gtid;
        if (t < NNZCM) {
            int r = Wcm_row[t];
            int c = Wcm_col[t];
            float v = Wcm_data[t] * __ldg(&cmw[r]);
            int s = atomicAdd(&g_rcnt[r], 1);
            if (s < CAP) g_rpak[r * CAP + s] = make_int2(c, __float_as_int(v));
            int s2 = atomicAdd(&g_ccnt[c], 1);
            if (s2 < CAP) g_cpak[c * CAP + s2] = make_int2(r, __float_as_int(v));
            atomicAdd(&g_rowsum[r], v);
        } else if (t < NNZCM + MLOC * 9) {
            int u = t - NNZCM;
            int m = u & (MLOC - 1);
            int j = u >> 11;                    // MLOC = 2048
            const int offs[9] = { -1 - WW, -1, -1 + WW, -WW, 0, WW, 1 - WW, 1, 1 + WW };
            int base = __ldg(&LOC_inInd[m]);
            int r0 = base + offs[0];
            int c  = base + offs[j];
            float h = 0.5f * __ldg(&LOC_flows[(size_t)j * 9 * MLOC + m]) * __ldg(&locw[base]);
            push_e(r0, c, -h);
            push_e(c, r0, -h);
            atomicAdd(&g_ediag[r0], h);
            atomicAdd(&g_ediag[c],  h);
        } else if (t < NWORK) {
            int u = t - NNZCM - MLOC * 9;
            int m = u / 5;
            int j = u - m * 5;
            int r = __ldg(&IU_inInd[m]);
            int c = __ldg(&IU_neigh[m * 5 + j]);
            float h = 0.5f * __ldg(&IU_flows[m * 5 + j]) * __ldg(&iuw[r]);
            push_e(r, c, -h);
            push_e(c, r, -h);
            atomicAdd(&g_ediag[r], h);
            atomicAdd(&g_ediag[c], h);
        }
    }
    grid_barrier(1);

    // ---- Phase 2: assemble rows r = blk, blk+GRID, ... (exactly 4/block) ----
    __shared__ float buf[NV];                  // 16 KB row accumulator
    __shared__ int   s_k [CAP + 1];            // staged outer entries of T(r)
    __shared__ float s_w [CAP + 1];
    __shared__ int   s_nk[CAP + 1];
    __shared__ float s_rs[CAP + 1];
    float4* buf4 = (float4*)buf;
    const int wid  = tid >> 5;                 // 0..7
    const int lane = tid & 31;
    const float4 z = make_float4(0.f, 0.f, 0.f, 0.f);
    const float lam = __ldg(&lmbda[0]);
    const uint32_t buf_s = smem_u32(buf);

    for (int r = blk; r < NV; r += GRID) {
        // Wait for the previous TMA read of buf before reuse.
        if (tid == 0)
            asm volatile("cp.async.bulk.wait_group.read 0;" ::: "memory");
        __syncthreads();

        // Stage A: batch-load ALL outer entries (k, w) and their (nk, rowsum)
        // into SMEM; latency overlaps the buffer-zero loop below.
        int tc = min(__ldcg(&g_ccnt[r]), CAP);
        if (tid <= tc) {
            int k; float w;
            if (tid < tc) {
                int2 p = __ldcg(&g_cpak[r * CAP + tid]);
                k = p.x; w = -__int_as_float(p.y);
            } else {
                k = r; w = __ldcg(&g_rowsum[r]);       // diagonal of col r
            }
            s_k[tid]  = k;
            s_w[tid]  = w;
            s_nk[tid] = min(__ldcg(&g_rcnt[k]), CAP);
            s_rs[tid] = __ldcg(&g_rowsum[k]);
        }
        for (int i = tid; i < NV / 4; i += NTHR) buf4[i] = z;
        __syncthreads();

        // Stage B: warp per outer entry; 8 warps -> rounds o = wid + 8j.
        // Prefetch the first inner batch of up to NPRE rounds back-to-back
        // (MLP), then burst the atomics.
        int2 pre[NPRE];
        #pragma unroll
        for (int j = 0; j < NPRE; j++) {
            int o = wid + j * 8;
            if (o <= tc && lane < s_nk[o])
                pre[j] = __ldcg(&g_rpak[s_k[o] * CAP + lane]);
        }
        #pragma unroll
        for (int j = 0; j < NPRE; j++) {
            int o = wid + j * 8;
            if (o > tc) break;
            int   k  = s_k[o];
            float w  = s_w[o];
            int   nk = s_nk[o];
            if (lane <= nk) {
                int c2; float v2;
                if (lane < nk) { c2 = pre[j].x; v2 = -__int_as_float(pre[j].y); }
                else           { c2 = k;        v2 = s_rs[o]; }   // diag of row k
                atomicAdd(&buf[c2], w * v2);
            }
            for (int i = lane + 32; i <= nk; i += 32) {           // rare tail
                int c2; float v2;
                if (i < nk) {
                    int2 q = __ldcg(&g_rpak[k * CAP + i]);
                    c2 = q.x; v2 = -__int_as_float(q.y);
                } else { c2 = k; v2 = s_rs[o]; }
                atomicAdd(&buf[c2], w * v2);
            }
        }
        for (int o = wid + NPRE * 8; o <= tc; o += 8) {           // tc > 31: rare
            int   k  = s_k[o];
            float w  = s_w[o];
            int   nk = s_nk[o];
            for (int i = lane; i <= nk; i += 32) {
                int c2; float v2;
                if (i < nk) {
                    int2 q = __ldcg(&g_rpak[k * CAP + i]);
                    c2 = q.x; v2 = -__int_as_float(q.y);
                } else { c2 = k; v2 = s_rs[o]; }
                atomicAdd(&buf[c2], w * v2);
            }
        }

        // binned LOC/IU off-diagonal contributions
        int ne = min(__ldcg(&g_ecnt[r]), ECAP);
        for (int i = tid; i < ne; i += NTHR) {
            int2 q = __ldcg(&g_epak[r * ECAP + i]);
            atomicAdd(&buf[q.x], __int_as_float(q.y));
        }

        // diagonal (LOC/IU diag + regularization) + RHS
        if (tid == 0) {
            float d = __ldg(&kuw[r]) * __ldg(&kToUconf[r]) + lam * __ldg(&known[r]);
            atomicAdd(&buf[r], d + __ldcg(&g_ediag[r]));
            b[r] = d * __ldg(&kToU[r]);
        }
        __syncthreads();

        // TMA bulk store: 16 KB SMEM row -> GMEM, off the warp-issue path.
        if (tid == 0) {
            asm volatile("fence.proxy.async.shared::cta;" ::: "memory");
            asm volatile(
                "cp.async.bulk.global.shared::cta.bulk_group [%0], [%1], %2;"
                :: "l"(A + (size_t)r * NV), "r"(buf_s), "n"(NV * 4)
                : "memory");
            asm volatile("cp.async.bulk.commit_group;" ::: "memory");
        }
        // next iteration begins with wait_group.read + syncthreads
    }

    // Drain outstanding TMA stores before exit.
    if (tid == 0)
        asm volatile("cp.async.bulk.wait_group 0;" ::: "memory");

    // ---- Reset barrier state for the next call (last finisher) ----
    if (tid == 0) {
        __threadfence();
        unsigned t = atomicAdd(&g_fin, 1);
        if (t == GRID - 1) {
            g_barc[0] = 0; g_barc[1] = 0;
            g_rel[0]  = 0; g_rel[1]  = 0;
            __threadfence();
            g_fin = 0;
        }
    }
}

// ---------------------------------------------------------------------------
extern "C" void kernel_launch(void* const* d_in, const int* in_sizes, int n_in,
                              void* d_out, int out_size) {
    const float* CM_weights  = (const float*)d_in[2];
    const float* LOC_weights = (const float*)d_in[3];
    const float* IU_weights  = (const float*)d_in[4];
    const float* KU_weights  = (const float*)d_in[5];
    const float* lmbda       = (const float*)d_in[6];
    const float* kToUconf    = (const float*)d_in[7];
    const float* known       = (const float*)d_in[8];
    const float* kToU        = (const float*)d_in[9];
    const int*   Wcm_row     = (const int*)d_in[10];
    const int*   Wcm_col     = (const int*)d_in[11];
    const float* Wcm_data    = (const float*)d_in[12];
    const int*   LOC_inInd   = (const int*)d_in[13];
    const float* LOC_flows   = (const float*)d_in[14];
    const int*   IU_inInd    = (const int*)d_in[15];
    const float* IU_flows    = (const float*)d_in[16];
    const int*   IU_neighInd = (const int*)d_in[17];

    float* A = (float*)d_out;
    float* b = (float*)d_out + (size_t)NV * NV;

    k_all<<<GRID, NTHR>>>(A, b,
                          Wcm_row, Wcm_col, Wcm_data, CM_weights,
                          LOC_inInd, LOC_flows, LOC_weights,
                          IU_inInd, IU_flows, IU_neighInd, IU_weights,
                          KU_weights, kToUconf, known, kToU, lmbda);
}